// round 4
// baseline (speedup 1.0000x reference)
#include <cuda_runtime.h>
#include <math.h>

#define B 64
#define S 64
#define L 64
#define H 1024
#define CDIM 2048
#define E 512
#define OC (H + E + CDIM)   // 3584
#define XK (E + CDIM)       // 2560
#define G3 (3 * H)          // 3072

#define NBLK 296
#define NTHR 256

// ---------------- scratch (device globals) ----------------------------------
__device__ float g_ctxproj[B * L * H];            // 16.8 MB
__device__ float g_giemb[(size_t)B * S * G3];     // 50.3 MB
__device__ float g_h[B * H];
__device__ float g_qpart[8 * B * H];              // split-K partials of q
__device__ float g_gipart[8 * (size_t)B * G3];    // split-K partials of gi(ctx)
__device__ float g_ghpart[4 * (size_t)B * G3];    // split-K partials of gh

// ---------------- grid barrier ----------------------------------------------
__device__ volatile unsigned g_gen;
__device__ unsigned g_cnt;

__device__ __forceinline__ void gsync() {
    __syncthreads();
    if (threadIdx.x == 0) {
        unsigned g = g_gen;
        __threadfence();
        if (atomicAdd(&g_cnt, 1u) == NBLK - 1) {
            g_cnt = 0;
            __threadfence();
            g_gen = g + 1;
        } else {
            int spins = 0;
            while (g_gen == g) {
                if (++spins > 64) __nanosleep(32);
            }
        }
        __threadfence();
    }
    __syncthreads();
}

// ---------------- FFMA-only fast tanh ----------------------------------------
__device__ __forceinline__ float tanh_fast(float x) {
    float y = fminf(fmaxf(x * 2.885390081777927f, -28.f), 28.f);
    float tt = y + 12582912.f;
    int   ik = __float_as_int(tt) - 0x4B400000;
    float f  = y - (tt - 12582912.f);
    float p  = 1.5403530393e-4f;
    p = fmaf(p, f, 1.3333558146e-3f);
    p = fmaf(p, f, 9.6181291076e-3f);
    p = fmaf(p, f, 5.5504108664e-2f);
    p = fmaf(p, f, 2.4022650696e-1f);
    p = fmaf(p, f, 6.9314718056e-1f);
    p = fmaf(p, f, 1.0f);
    float e = __int_as_float(__float_as_int(p) + (ik << 23));
    float d = e + 1.0f;
    float r = __int_as_float(0x7EF311C3 - __float_as_int(d));
    r = r * (2.0f - d * r);
    r = r * (2.0f - d * r);
    return (e - 1.0f) * r;
}

// ---------------- tf32 mma helpers -------------------------------------------
__device__ __forceinline__ unsigned f2tf32(float x) {
    unsigned y;
    asm("cvt.rna.tf32.f32 %0, %1;" : "=r"(y) : "f"(x));
    return y;
}
__device__ __forceinline__ void mma_tf32(float* c, const unsigned* a, const unsigned* b) {
    asm volatile(
        "mma.sync.aligned.m16n8k8.row.col.f32.tf32.tf32.f32 "
        "{%0,%1,%2,%3},{%4,%5,%6,%7},{%8,%9},{%0,%1,%2,%3};"
        : "+f"(c[0]), "+f"(c[1]), "+f"(c[2]), "+f"(c[3])
        : "r"(a[0]), "r"(a[1]), "r"(a[2]), "r"(a[3]), "r"(b[0]), "r"(b[1]));
}

// ---------------- tf32 GEMM body: C[64, n0:n0+128] = A @ B^T (k0..k1) --------
__device__ __forceinline__ void gemm_body(
    const float* __restrict__ A, int lda,
    const float* __restrict__ Bm, int ldb,
    float* __restrict__ C, int ldc,
    int m0, int n0, int k0, int k1)
{
    __shared__ unsigned As[64 * 32];
    __shared__ unsigned Bs[128 * 32];

    const int tid  = threadIdx.x;
    const int lane = tid & 31;
    const int warp = tid >> 5;
    const int wm = warp >> 2;
    const int wn = warp & 3;
    const int fr = lane >> 2;
    const int fc = lane & 3;

    float acc[2][4][4];
#pragma unroll
    for (int mi = 0; mi < 2; mi++)
#pragma unroll
        for (int ni = 0; ni < 4; ni++)
#pragma unroll
            for (int j = 0; j < 4; j++) acc[mi][ni][j] = 0.f;

    for (int kb = k0; kb < k1; kb += 32) {
        float4 av[2], bv[4];
#pragma unroll
        for (int i = 0; i < 2; i++) {
            int idx = tid + i * 256;
            av[i] = *(const float4*)(A + (size_t)(m0 + (idx >> 3)) * lda + kb + (idx & 7) * 4);
        }
#pragma unroll
        for (int i = 0; i < 4; i++) {
            int idx = tid + i * 256;
            bv[i] = *(const float4*)(Bm + (size_t)(n0 + (idx >> 3)) * ldb + kb + (idx & 7) * 4);
        }
        __syncthreads();
#pragma unroll
        for (int i = 0; i < 2; i++) {
            int idx = tid + i * 256;
            int rr = idx >> 3, kq = idx & 7;
            unsigned* dst = &As[rr * 32 + ((kq ^ (rr & 7)) << 2)];
            dst[0] = f2tf32(av[i].x); dst[1] = f2tf32(av[i].y);
            dst[2] = f2tf32(av[i].z); dst[3] = f2tf32(av[i].w);
        }
#pragma unroll
        for (int i = 0; i < 4; i++) {
            int idx = tid + i * 256;
            int rr = idx >> 3, kq = idx & 7;
            unsigned* dst = &Bs[rr * 32 + ((kq ^ (rr & 7)) << 2)];
            dst[0] = f2tf32(bv[i].x); dst[1] = f2tf32(bv[i].y);
            dst[2] = f2tf32(bv[i].z); dst[3] = f2tf32(bv[i].w);
        }
        __syncthreads();

#pragma unroll
        for (int ks = 0; ks < 4; ks++) {
            unsigned afr[2][4], bfr[4][2];
#pragma unroll
            for (int mi = 0; mi < 2; mi++) {
                int r0 = wm * 32 + mi * 16 + fr;
                int r1 = r0 + 8;
                int g0 = ((ks * 2)     ^ (r0 & 7)) << 2;
                int g1 = ((ks * 2 + 1) ^ (r0 & 7)) << 2;
                afr[mi][0] = As[r0 * 32 + g0 + fc];
                afr[mi][1] = As[r1 * 32 + g0 + fc];
                afr[mi][2] = As[r0 * 32 + g1 + fc];
                afr[mi][3] = As[r1 * 32 + g1 + fc];
            }
#pragma unroll
            for (int ni = 0; ni < 4; ni++) {
                int nr = wn * 32 + ni * 8 + fr;
                int g0 = ((ks * 2)     ^ (nr & 7)) << 2;
                int g1 = ((ks * 2 + 1) ^ (nr & 7)) << 2;
                bfr[ni][0] = Bs[nr * 32 + g0 + fc];
                bfr[ni][1] = Bs[nr * 32 + g1 + fc];
            }
#pragma unroll
            for (int mi = 0; mi < 2; mi++)
#pragma unroll
                for (int ni = 0; ni < 4; ni++)
                    mma_tf32(acc[mi][ni], afr[mi], bfr[ni]);
        }
        __syncthreads();
    }

#pragma unroll
    for (int mi = 0; mi < 2; mi++) {
        int row = m0 + wm * 32 + mi * 16 + fr;
#pragma unroll
        for (int ni = 0; ni < 4; ni++) {
            int col = n0 + wn * 32 + ni * 8 + fc * 2;
            *(float2*)&C[(size_t)row * ldc + col] =
                make_float2(acc[mi][ni][0], acc[mi][ni][1]);
            *(float2*)&C[(size_t)(row + 8) * ldc + col] =
                make_float2(acc[mi][ni][2], acc[mi][ni][3]);
        }
    }
}

// ---------------- precompute GEMM kernel --------------------------------------
__global__ __launch_bounds__(256) void gemm_pre(
    const float* __restrict__ A, int lda,
    const float* __restrict__ Bm, int ldb,
    float* __restrict__ C, int ldc, int K) {
    gemm_body(A, lda, Bm, ldb, C, ldc, blockIdx.y * 64, blockIdx.x * 128, 0, K);
}

// ---------------- init / embedding -------------------------------------------
__global__ void k_init(const float* __restrict__ h0) {
    int i = blockIdx.x * 256 + threadIdx.x;
    if (i < B * H) g_h[i] = h0[i];
}
__global__ void k_emb(const int* __restrict__ tgt,
                      const float* __restrict__ emb,
                      float* __restrict__ out) {
    int row = blockIdx.x;
    int tok = tgt[row];
    const float4* src = (const float4*)(emb + (size_t)tok * E);
    float4* dst = (float4*)(out + (size_t)row * OC + H);
    dst[threadIdx.x] = src[threadIdx.x];
}

// ---------------- persistent step loop ----------------------------------------
__global__ __launch_bounds__(NTHR, 2)
void k_persist(const float* __restrict__ ctx,
               const float* __restrict__ Wq,
               const float* __restrict__ bq,
               const float* __restrict__ v,
               const float* __restrict__ W_ih,
               const float* __restrict__ W_hh,
               const float* __restrict__ b_ih,
               const float* __restrict__ b_hh,
               float* out)
{
    const int bid = blockIdx.x;
    const int tid = threadIdx.x;

    __shared__ float s_q[H];        // 4 KB (reused by BC phase)
    __shared__ float s_v[H];        // 4 KB
    __shared__ float s_attn[L];

    for (int t = 0; t < S; t++) {
        // ======== Phase A: q partials (64 tasks) + gh partials (96 tasks) =====
        if (bid < 64) {
            int nt = bid & 7, ks = bid >> 3;                // kc = 128
            gemm_body(g_h, H, Wq, H, g_qpart + ks * (B * H), H,
                      0, nt * 128, ks * 128, ks * 128 + 128);
        } else if (bid < 160) {
            int u = bid - 64;
            int nt = u % 24, ks = u / 24;                    // kc = 256
            gemm_body(g_h, H, W_hh, H,
                      g_ghpart + (size_t)ks * (B * G3), G3,
                      0, nt * 128, ks * 256, ks * 256 + 256);
        }
        gsync();

        // ======== Phase BC: scores + softmax + ctx_t (one block per batch) ====
        if (bid < 64) {
            const int b = bid;
            // reduce q partials (+bq) into smem; stage v
            {
                float4 q = ((const float4*)bq)[tid];
#pragma unroll
                for (int p = 0; p < 8; p++) {
                    float4 qp = ((const float4*)(g_qpart + p * (B * H) + b * H))[tid];
                    q.x += qp.x; q.y += qp.y; q.z += qp.z; q.w += qp.w;
                }
                ((float4*)s_q)[tid] = q;
                ((float4*)s_v)[tid] = ((const float4*)v)[tid];
            }
            __syncthreads();

            // scores: warp w handles rows l = w, w+8, ...
            {
                const int w = tid >> 5, lane = tid & 31;
                for (int l = w; l < L; l += 8) {
                    const float4* cp = (const float4*)(g_ctxproj + ((size_t)(b * L + l)) * H);
                    float acc = 0.f;
#pragma unroll
                    for (int i = 0; i < 8; i++) {
                        int c4 = i * 32 + lane;
                        float4 c = cp[c4];
                        float4 q = ((const float4*)s_q)[c4];
                        float4 vv = ((const float4*)s_v)[c4];
                        acc += vv.x * tanh_fast(c.x + q.x) + vv.y * tanh_fast(c.y + q.y)
                             + vv.z * tanh_fast(c.z + q.z) + vv.w * tanh_fast(c.w + q.w);
                    }
#pragma unroll
                    for (int o = 16; o; o >>= 1) acc += __shfl_xor_sync(0xffffffffu, acc, o);
                    if (lane == 0) s_attn[l] = acc;
                }
            }
            __syncthreads();

            // softmax (warp 0)
            if (tid < 32) {
                float s0 = s_attn[tid], s1 = s_attn[tid + 32];
                float m = fmaxf(s0, s1);
#pragma unroll
                for (int o = 16; o; o >>= 1) m = fmaxf(m, __shfl_xor_sync(0xffffffffu, m, o));
                float e0 = __expf(s0 - m), e1 = __expf(s1 - m);
                float ss = e0 + e1;
#pragma unroll
                for (int o = 16; o; o >>= 1) ss += __shfl_xor_sync(0xffffffffu, ss, o);
                s_attn[tid] = e0 / ss; s_attn[tid + 32] = e1 / ss;
            }
            __syncthreads();

            // ctx_t -> out cols [H+E, OC)
            {
                const float4* cb4 = (const float4*)(ctx + (size_t)b * L * CDIM);
                float4* orow4 = (float4*)(out + ((size_t)(b * S + t)) * OC + H + E);
#pragma unroll
                for (int rep = 0; rep < 2; rep++) {
                    int c4 = rep * 256 + tid;
                    float4 acc = {0.f, 0.f, 0.f, 0.f};
#pragma unroll 8
                    for (int l = 0; l < L; l++) {
                        float a = s_attn[l];
                        float4 x = cb4[(size_t)l * (CDIM / 4) + c4];
                        acc.x = fmaf(a, x.x, acc.x); acc.y = fmaf(a, x.y, acc.y);
                        acc.z = fmaf(a, x.z, acc.z); acc.w = fmaf(a, x.w, acc.w);
                    }
                    orow4[c4] = acc;
                }
            }
        }
        gsync();

        // ======== Phase D: gi partials (192 tasks, kc=256) =====================
        if (bid < 192) {
            int nt = bid % 24, ks = bid / 24;
            gemm_body(out + (size_t)t * OC + (H + E), S * OC,
                      W_ih + E, XK,
                      g_gipart + (size_t)ks * (B * G3), G3,
                      0, nt * 128, ks * 256, ks * 256 + 256);
        }
        gsync();

        // ======== Phase E: GRU update ==========================================
        {
            int idx = bid * NTHR + tid;
            if (idx < B * H) {
                int b = idx >> 10, i = idx & (H - 1);
                size_t ge = ((size_t)(b * S + t)) * G3;
                float ir  = b_ih[i]         + g_giemb[ge + i];
                float iz  = b_ih[H + i]     + g_giemb[ge + H + i];
                float in_ = b_ih[2 * H + i] + g_giemb[ge + 2 * H + i];
#pragma unroll
                for (int p = 0; p < 8; p++) {
                    const float* gp = g_gipart + (size_t)p * (B * G3) + (size_t)b * G3;
                    ir += gp[i]; iz += gp[H + i]; in_ += gp[2 * H + i];
                }
                float hr = b_hh[i], hz = b_hh[H + i], hn = b_hh[2 * H + i];
#pragma unroll
                for (int p = 0; p < 4; p++) {
                    const float* gp = g_ghpart + (size_t)p * (B * G3) + (size_t)b * G3;
                    hr += gp[i]; hz += gp[H + i]; hn += gp[2 * H + i];
                }
                float r = 1.f / (1.f + __expf(-(ir + hr)));
                float z = 1.f / (1.f + __expf(-(iz + hz)));
                float n = tanh_fast(in_ + r * hn);
                float hold = g_h[idx];
                float hnew = (1.f - z) * n + z * hold;
                g_h[idx] = hnew;
                out[((size_t)(b * S + t)) * OC + i] = hold;
            }
        }
        gsync();
    }

    // ---- final hidden state ----
    {
        int idx = bid * NTHR + tid;
        if (idx < B * H) out[(size_t)B * S * OC + idx] = g_h[idx];
    }
}

// -----------------------------------------------------------------------------
extern "C" void kernel_launch(void* const* d_in, const int* in_sizes, int n_in,
                              void* d_out, int out_size) {
    const int*   tgt  = (const int*)d_in[0];
    const float* ctx  = (const float*)d_in[1];
    const float* h0   = (const float*)d_in[2];
    const float* emb  = (const float*)d_in[3];
    const float* Wc   = (const float*)d_in[4];
    const float* Wq   = (const float*)d_in[5];
    const float* bq   = (const float*)d_in[6];
    const float* v    = (const float*)d_in[7];
    const float* W_ih = (const float*)d_in[8];
    const float* W_hh = (const float*)d_in[9];
    const float* b_ih = (const float*)d_in[10];
    const float* b_hh = (const float*)d_in[11];
    float* out = (float*)d_out;

    float *p_cp, *p_ge;
    cudaGetSymbolAddress((void**)&p_cp, g_ctxproj);
    cudaGetSymbolAddress((void**)&p_ge, g_giemb);

    k_init<<<(B * H) / 256, 256>>>(h0);
    k_emb<<<B * S, 128>>>(tgt, emb, out);

    // ctx_proj[B*L, H] = ctx @ Wc^T
    gemm_pre<<<dim3(H / 128, (B * L) / 64), 256>>>(ctx, CDIM, Wc, CDIM, p_cp, H, CDIM);
    // gi_emb[B*S, 3H] = emb_rows @ W_ih[:, :E]^T
    gemm_pre<<<dim3(G3 / 128, (B * S) / 64), 256>>>(out + H, OC, W_ih, XK, p_ge, G3, E);

    // whole 64-step loop in one persistent kernel
    k_persist<<<NBLK, NTHR>>>(ctx, Wq, bq, v, W_ih, W_hh, b_ih, b_hh, out);
}

// round 5
// speedup vs baseline: 1.6640x; 1.6640x over previous
#include <cuda_runtime.h>
#include <math.h>

#define B 64
#define S 64
#define L 64
#define H 1024
#define CDIM 2048
#define E 512
#define OC (H + E + CDIM)   // 3584
#define XK (E + CDIM)       // 2560
#define G3 (3 * H)          // 3072
#define BH (B * H)
#define BG3 (B * G3)

// ---------------- scratch (device globals) ----------------------------------
__device__ float g_ctxproj[B * L * H];            // 16.8 MB
__device__ float g_giemb[(size_t)B * S * G3];     // 50.3 MB
__device__ float g_h[BH];                         // full-precision hidden
__device__ float g_hr[BH];                        // tf32-rounded hidden (GEMM A)
__device__ float g_ctxt[B * CDIM];                // tf32-rounded ctx_t (GEMM A)
__device__ float g_qpart[8 * BH];                 // split-K partials of q
__device__ float g_gipart[8 * (size_t)BG3];       // split-K partials of gi(ctx)
__device__ float g_ghpart[4 * (size_t)BG3];       // split-K partials of gh
// pre-rounded weights
__device__ float g_Wq[H * H];                     // 4.2 MB
__device__ float g_Whh[G3 * H];                   // 12.6 MB
__device__ float g_Wihc[(size_t)G3 * CDIM];       // 25.2 MB

// ---------------- helpers ----------------------------------------------------
__device__ __forceinline__ unsigned f2tf32(float x) {
    unsigned y;
    asm("cvt.rna.tf32.f32 %0, %1;" : "=r"(y) : "f"(x));
    return y;
}
__device__ __forceinline__ float round_tf32(float x) {
    return __uint_as_float(f2tf32(x));
}
__device__ __forceinline__ void mma_tf32(float* c, const unsigned* a, const unsigned* b) {
    asm volatile(
        "mma.sync.aligned.m16n8k8.row.col.f32.tf32.tf32.f32 "
        "{%0,%1,%2,%3},{%4,%5,%6,%7},{%8,%9},{%0,%1,%2,%3};"
        : "+f"(c[0]), "+f"(c[1]), "+f"(c[2]), "+f"(c[3])
        : "r"(a[0]), "r"(a[1]), "r"(a[2]), "r"(a[3]), "r"(b[0]), "r"(b[1]));
}
__device__ __forceinline__ void cp_async16(unsigned dst, const void* src) {
    asm volatile("cp.async.cg.shared.global [%0], [%1], 16;" :: "r"(dst), "l"(src));
}
__device__ __forceinline__ void cp_commit() {
    asm volatile("cp.async.commit_group;");
}
__device__ __forceinline__ void cp_wait1() {
    asm volatile("cp.async.wait_group 1;");
}
__device__ __forceinline__ void cp_wait0() {
    asm volatile("cp.async.wait_group 0;");
}

// ---------------- FFMA-only fast tanh ----------------------------------------
__device__ __forceinline__ float tanh_fast(float x) {
    float y = fminf(fmaxf(x * 2.885390081777927f, -28.f), 28.f);
    float tt = y + 12582912.f;
    int   ik = __float_as_int(tt) - 0x4B400000;
    float f  = y - (tt - 12582912.f);
    float p  = 1.5403530393e-4f;
    p = fmaf(p, f, 1.3333558146e-3f);
    p = fmaf(p, f, 9.6181291076e-3f);
    p = fmaf(p, f, 5.5504108664e-2f);
    p = fmaf(p, f, 2.4022650696e-1f);
    p = fmaf(p, f, 6.9314718056e-1f);
    p = fmaf(p, f, 1.0f);
    float e = __int_as_float(__float_as_int(p) + (ik << 23));
    float d = e + 1.0f;
    float r = __int_as_float(0x7EF311C3 - __float_as_int(d));
    r = r * (2.0f - d * r);
    r = r * (2.0f - d * r);
    return (e - 1.0f) * r;
}

// ---------------- 2-stage cp.async tf32 GEMM ---------------------------------
// C[64, n0:n0+128] = A[64, k0:...] @ B[n0:n0+128, k0:...]^T
// Operands MUST be pre-rounded tf32 values. 256 threads, BK=32.
__device__ __forceinline__ void gemm_issue(
    unsigned a_base, unsigned b_base,
    const float* __restrict__ A, int lda,
    const float* __restrict__ Bm, int ldb,
    int n0, int kb, int tid)
{
#pragma unroll
    for (int i = 0; i < 2; i++) {
        int idx = tid + i * 256;
        int rr = idx >> 3, kq = idx & 7;
        cp_async16(a_base + (unsigned)((rr * 32 + ((kq ^ (rr & 7)) << 2)) * 4),
                   A + (size_t)rr * lda + kb + kq * 4);
    }
#pragma unroll
    for (int i = 0; i < 4; i++) {
        int idx = tid + i * 256;
        int rr = idx >> 3, kq = idx & 7;
        cp_async16(b_base + (unsigned)((rr * 32 + ((kq ^ (rr & 7)) << 2)) * 4),
                   Bm + (size_t)(n0 + rr) * ldb + kb + kq * 4);
    }
    cp_commit();
}

template <int NITER>
__device__ __forceinline__ void gemm_async(
    const float* __restrict__ A, int lda,
    const float* __restrict__ Bm, int ldb,
    float* __restrict__ C, int ldc,
    int n0, int k0)
{
    __shared__ float As[2][64 * 32];
    __shared__ float Bs[2][128 * 32];

    const int tid  = threadIdx.x;
    const int lane = tid & 31;
    const int warp = tid >> 5;
    const int wm = warp >> 2;
    const int wn = warp & 3;
    const int fr = lane >> 2;
    const int fc = lane & 3;

    unsigned sA = (unsigned)__cvta_generic_to_shared(&As[0][0]);
    unsigned sB = (unsigned)__cvta_generic_to_shared(&Bs[0][0]);

    float acc[2][4][4];
#pragma unroll
    for (int mi = 0; mi < 2; mi++)
#pragma unroll
        for (int ni = 0; ni < 4; ni++)
#pragma unroll
            for (int j = 0; j < 4; j++) acc[mi][ni][j] = 0.f;

    gemm_issue(sA, sB, A, lda, Bm, ldb, n0, k0, tid);

#pragma unroll
    for (int it = 0; it < NITER; it++) {
        if (it + 1 < NITER) {
            int st = (it + 1) & 1;
            gemm_issue(sA + st * 64 * 32 * 4, sB + st * 128 * 32 * 4,
                       A, lda, Bm, ldb, n0, k0 + (it + 1) * 32, tid);
            cp_wait1();
        } else {
            cp_wait0();
        }
        __syncthreads();

        const unsigned* as = (const unsigned*)As[it & 1];
        const unsigned* bs = (const unsigned*)Bs[it & 1];
#pragma unroll
        for (int ks = 0; ks < 4; ks++) {
            unsigned afr[2][4], bfr[4][2];
#pragma unroll
            for (int mi = 0; mi < 2; mi++) {
                int r0 = wm * 32 + mi * 16 + fr;
                int r1 = r0 + 8;
                int g0 = ((ks * 2)     ^ (r0 & 7)) << 2;
                int g1 = ((ks * 2 + 1) ^ (r0 & 7)) << 2;
                afr[mi][0] = as[r0 * 32 + g0 + fc];
                afr[mi][1] = as[r1 * 32 + g0 + fc];
                afr[mi][2] = as[r0 * 32 + g1 + fc];
                afr[mi][3] = as[r1 * 32 + g1 + fc];
            }
#pragma unroll
            for (int ni = 0; ni < 4; ni++) {
                int nr = wn * 32 + ni * 8 + fr;
                int g0 = ((ks * 2)     ^ (nr & 7)) << 2;
                int g1 = ((ks * 2 + 1) ^ (nr & 7)) << 2;
                bfr[ni][0] = bs[nr * 32 + g0 + fc];
                bfr[ni][1] = bs[nr * 32 + g1 + fc];
            }
#pragma unroll
            for (int mi = 0; mi < 2; mi++)
#pragma unroll
                for (int ni = 0; ni < 4; ni++)
                    mma_tf32(acc[mi][ni], afr[mi], bfr[ni]);
        }
        __syncthreads();
    }

#pragma unroll
    for (int mi = 0; mi < 2; mi++) {
        int row = wm * 32 + mi * 16 + fr;
#pragma unroll
        for (int ni = 0; ni < 4; ni++) {
            int col = n0 + wn * 32 + ni * 8 + fc * 2;
            *(float2*)&C[(size_t)row * ldc + col] =
                make_float2(acc[mi][ni][0], acc[mi][ni][1]);
            *(float2*)&C[(size_t)(row + 8) * ldc + col] =
                make_float2(acc[mi][ni][2], acc[mi][ni][3]);
        }
    }
}

// ---------------- legacy cvt-path GEMM (precompute only) ---------------------
__device__ __forceinline__ void gemm_body(
    const float* __restrict__ A, int lda,
    const float* __restrict__ Bm, int ldb,
    float* __restrict__ C, int ldc,
    int m0, int n0, int k0, int k1)
{
    __shared__ unsigned As[64 * 32];
    __shared__ unsigned Bs[128 * 32];

    const int tid  = threadIdx.x;
    const int lane = tid & 31;
    const int warp = tid >> 5;
    const int wm = warp >> 2;
    const int wn = warp & 3;
    const int fr = lane >> 2;
    const int fc = lane & 3;

    float acc[2][4][4];
#pragma unroll
    for (int mi = 0; mi < 2; mi++)
#pragma unroll
        for (int ni = 0; ni < 4; ni++)
#pragma unroll
            for (int j = 0; j < 4; j++) acc[mi][ni][j] = 0.f;

    for (int kb = k0; kb < k1; kb += 32) {
        float4 av[2], bv[4];
#pragma unroll
        for (int i = 0; i < 2; i++) {
            int idx = tid + i * 256;
            av[i] = *(const float4*)(A + (size_t)(m0 + (idx >> 3)) * lda + kb + (idx & 7) * 4);
        }
#pragma unroll
        for (int i = 0; i < 4; i++) {
            int idx = tid + i * 256;
            bv[i] = *(const float4*)(Bm + (size_t)(n0 + (idx >> 3)) * ldb + kb + (idx & 7) * 4);
        }
        __syncthreads();
#pragma unroll
        for (int i = 0; i < 2; i++) {
            int idx = tid + i * 256;
            int rr = idx >> 3, kq = idx & 7;
            unsigned* dst = &As[rr * 32 + ((kq ^ (rr & 7)) << 2)];
            dst[0] = f2tf32(av[i].x); dst[1] = f2tf32(av[i].y);
            dst[2] = f2tf32(av[i].z); dst[3] = f2tf32(av[i].w);
        }
#pragma unroll
        for (int i = 0; i < 4; i++) {
            int idx = tid + i * 256;
            int rr = idx >> 3, kq = idx & 7;
            unsigned* dst = &Bs[rr * 32 + ((kq ^ (rr & 7)) << 2)];
            dst[0] = f2tf32(bv[i].x); dst[1] = f2tf32(bv[i].y);
            dst[2] = f2tf32(bv[i].z); dst[3] = f2tf32(bv[i].w);
        }
        __syncthreads();

#pragma unroll
        for (int ks = 0; ks < 4; ks++) {
            unsigned afr[2][4], bfr[4][2];
#pragma unroll
            for (int mi = 0; mi < 2; mi++) {
                int r0 = wm * 32 + mi * 16 + fr;
                int r1 = r0 + 8;
                int g0 = ((ks * 2)     ^ (r0 & 7)) << 2;
                int g1 = ((ks * 2 + 1) ^ (r0 & 7)) << 2;
                afr[mi][0] = As[r0 * 32 + g0 + fc];
                afr[mi][1] = As[r1 * 32 + g0 + fc];
                afr[mi][2] = As[r0 * 32 + g1 + fc];
                afr[mi][3] = As[r1 * 32 + g1 + fc];
            }
#pragma unroll
            for (int ni = 0; ni < 4; ni++) {
                int nr = wn * 32 + ni * 8 + fr;
                int g0 = ((ks * 2)     ^ (nr & 7)) << 2;
                int g1 = ((ks * 2 + 1) ^ (nr & 7)) << 2;
                bfr[ni][0] = Bs[nr * 32 + g0 + fc];
                bfr[ni][1] = Bs[nr * 32 + g1 + fc];
            }
#pragma unroll
            for (int mi = 0; mi < 2; mi++)
#pragma unroll
                for (int ni = 0; ni < 4; ni++)
                    mma_tf32(acc[mi][ni], afr[mi], bfr[ni]);
        }
        __syncthreads();
    }

#pragma unroll
    for (int mi = 0; mi < 2; mi++) {
        int row = m0 + wm * 32 + mi * 16 + fr;
#pragma unroll
        for (int ni = 0; ni < 4; ni++) {
            int col = n0 + wn * 32 + ni * 8 + fc * 2;
            *(float2*)&C[(size_t)row * ldc + col] =
                make_float2(acc[mi][ni][0], acc[mi][ni][1]);
            *(float2*)&C[(size_t)(row + 8) * ldc + col] =
                make_float2(acc[mi][ni][2], acc[mi][ni][3]);
        }
    }
}

__global__ __launch_bounds__(256) void gemm_pre(
    const float* __restrict__ A, int lda,
    const float* __restrict__ Bm, int ldb,
    float* __restrict__ C, int ldc, int K) {
    gemm_body(A, lda, Bm, ldb, C, ldc, blockIdx.y * 64, blockIdx.x * 128, 0, K);
}

// ---------------- prep: init h + pre-round weights ---------------------------
__global__ void k_prep(const float* __restrict__ h0,
                       const float* __restrict__ Wq,
                       const float* __restrict__ W_hh,
                       const float* __restrict__ W_ih) {
    int stride = gridDim.x * blockDim.x;
    int tid0 = blockIdx.x * blockDim.x + threadIdx.x;
    for (int i = tid0; i < BH; i += stride) {
        float h = h0[i];
        g_h[i] = h;
        g_hr[i] = round_tf32(h);
    }
    for (int i = tid0; i < H * H; i += stride)
        g_Wq[i] = round_tf32(Wq[i]);
    for (int i = tid0; i < G3 * H; i += stride)
        g_Whh[i] = round_tf32(W_hh[i]);
    for (size_t i = tid0; i < (size_t)G3 * CDIM; i += stride) {
        size_t r = i / CDIM, c = i - r * CDIM;
        g_Wihc[i] = round_tf32(W_ih[r * XK + E + c]);
    }
}

// ---------------- embedding gather -------------------------------------------
__global__ void k_emb(const int* __restrict__ tgt,
                      const float* __restrict__ emb,
                      float* __restrict__ out) {
    int row = blockIdx.x;
    int tok = tgt[row];
    const float4* src = (const float4*)(emb + (size_t)tok * E);
    float4* dst = (float4*)(out + (size_t)row * OC + H);
    dst[threadIdx.x] = src[threadIdx.x];
}

// ---------------- K1: q partials ----------------------------------------------
__global__ __launch_bounds__(256) void k1_q() {
    int nt = blockIdx.x & 7, ks = blockIdx.x >> 3;
    gemm_async<4>(g_hr, H, g_Wq, H, g_qpart + ks * BH, H, nt * 128, ks * 128);
}

// ---------------- K2: fused attention (1024 thr, 1 block per batch) -----------
__global__ __launch_bounds__(1024) void k2_attn(
    const float* __restrict__ ctx,
    const float* __restrict__ bq,
    const float* __restrict__ v,
    float* __restrict__ out, int t)
{
    const int b = blockIdx.x;
    const int tid = threadIdx.x;
    __shared__ float s_q[H];
    __shared__ float s_v[H];
    __shared__ float s_attn[L];

    // reduce q partials (+bq), stage v
    if (tid < 256) {
        float4 q = ((const float4*)bq)[tid];
#pragma unroll
        for (int p = 0; p < 8; p++) {
            float4 qp = ((const float4*)(g_qpart + p * BH + b * H))[tid];
            q.x += qp.x; q.y += qp.y; q.z += qp.z; q.w += qp.w;
        }
        ((float4*)s_q)[tid] = q;
        ((float4*)s_v)[tid] = ((const float4*)v)[tid];
    }
    __syncthreads();

    // scores: 32 warps, each 2 rows
    {
        const int w = tid >> 5, lane = tid & 31;
#pragma unroll
        for (int rep = 0; rep < 2; rep++) {
            int l = w + rep * 32;
            const float4* cp = (const float4*)(g_ctxproj + ((size_t)(b * L + l)) * H);
            float acc = 0.f;
#pragma unroll
            for (int i = 0; i < 8; i++) {
                int c4 = i * 32 + lane;
                float4 c = cp[c4];
                float4 q = ((const float4*)s_q)[c4];
                float4 vv = ((const float4*)s_v)[c4];
                acc += vv.x * tanh_fast(c.x + q.x) + vv.y * tanh_fast(c.y + q.y)
                     + vv.z * tanh_fast(c.z + q.z) + vv.w * tanh_fast(c.w + q.w);
            }
#pragma unroll
            for (int o = 16; o; o >>= 1) acc += __shfl_xor_sync(0xffffffffu, acc, o);
            if (lane == 0) s_attn[l] = acc;
        }
    }
    __syncthreads();

    // softmax (warp 0)
    if (tid < 32) {
        float s0 = s_attn[tid], s1 = s_attn[tid + 32];
        float m = fmaxf(s0, s1);
#pragma unroll
        for (int o = 16; o; o >>= 1) m = fmaxf(m, __shfl_xor_sync(0xffffffffu, m, o));
        float e0 = __expf(s0 - m), e1 = __expf(s1 - m);
        float ss = e0 + e1;
#pragma unroll
        for (int o = 16; o; o >>= 1) ss += __shfl_xor_sync(0xffffffffu, ss, o);
        s_attn[tid] = e0 / ss; s_attn[tid + 32] = e1 / ss;
    }
    __syncthreads();

    // ctx_t: 512 col4 handled by tid < 512
    if (tid < 512) {
        const float4* cb4 = (const float4*)(ctx + (size_t)b * L * CDIM);
        float4 acc = {0.f, 0.f, 0.f, 0.f};
#pragma unroll 8
        for (int l = 0; l < L; l++) {
            float a = s_attn[l];
            float4 x = cb4[(size_t)l * (CDIM / 4) + tid];
            acc.x = fmaf(a, x.x, acc.x); acc.y = fmaf(a, x.y, acc.y);
            acc.z = fmaf(a, x.z, acc.z); acc.w = fmaf(a, x.w, acc.w);
        }
        ((float4*)(out + ((size_t)(b * S + t)) * OC + H + E))[tid] = acc;
        float4 rr = {round_tf32(acc.x), round_tf32(acc.y),
                     round_tf32(acc.z), round_tf32(acc.w)};
        ((float4*)(g_ctxt + (size_t)b * CDIM))[tid] = rr;
    }
}

// ---------------- K3: gi + gh partials ----------------------------------------
__global__ __launch_bounds__(256) void k3_gates() {
    int bid = blockIdx.x;
    if (bid < 192) {
        int nt = bid % 24, ks = bid / 24;   // ks 0..7, kc=256
        gemm_async<8>(g_ctxt, CDIM, g_Wihc, CDIM,
                      g_gipart + (size_t)ks * BG3, G3, nt * 128, ks * 256);
    } else {
        int u = bid - 192;
        int nt = u % 24, ks = u / 24;        // ks 0..3, kc=256
        gemm_async<8>(g_hr, H, g_Whh, H,
                      g_ghpart + (size_t)ks * BG3, G3, nt * 128, ks * 256);
    }
}

// ---------------- K4: GRU update -----------------------------------------------
__global__ __launch_bounds__(256) void k4_update(
    const float* __restrict__ b_ih, const float* __restrict__ b_hh,
    float* __restrict__ out, int t)
{
    const int idx = blockIdx.x * 256 + threadIdx.x;   // b*H + i
    const int b = idx >> 10, i = idx & (H - 1);
    const size_t ge = ((size_t)(b * S + t)) * G3;

    float ir  = b_ih[i]         + g_giemb[ge + i];
    float iz  = b_ih[H + i]     + g_giemb[ge + H + i];
    float in_ = b_ih[2 * H + i] + g_giemb[ge + 2 * H + i];
#pragma unroll
    for (int p = 0; p < 8; p++) {
        const float* gp = g_gipart + (size_t)p * BG3 + (size_t)b * G3;
        ir += gp[i]; iz += gp[H + i]; in_ += gp[2 * H + i];
    }
    float hr = b_hh[i], hz = b_hh[H + i], hn = b_hh[2 * H + i];
#pragma unroll
    for (int p = 0; p < 4; p++) {
        const float* gp = g_ghpart + (size_t)p * BG3 + (size_t)b * G3;
        hr += gp[i]; hz += gp[H + i]; hn += gp[2 * H + i];
    }
    float r = 1.f / (1.f + __expf(-(ir + hr)));
    float z = 1.f / (1.f + __expf(-(iz + hz)));
    float n = tanh_fast(in_ + r * hn);
    float hold = g_h[idx];
    float hnew = (1.f - z) * n + z * hold;

    g_h[idx]  = hnew;
    g_hr[idx] = round_tf32(hnew);
    out[((size_t)(b * S + t)) * OC + i] = hold;
    if (t == S - 1)
        out[(size_t)B * S * OC + idx] = hnew;
}

// -----------------------------------------------------------------------------
extern "C" void kernel_launch(void* const* d_in, const int* in_sizes, int n_in,
                              void* d_out, int out_size) {
    const int*   tgt  = (const int*)d_in[0];
    const float* ctx  = (const float*)d_in[1];
    const float* h0   = (const float*)d_in[2];
    const float* emb  = (const float*)d_in[3];
    const float* Wc   = (const float*)d_in[4];
    const float* Wq   = (const float*)d_in[5];
    const float* bq   = (const float*)d_in[6];
    const float* v    = (const float*)d_in[7];
    const float* W_ih = (const float*)d_in[8];
    const float* W_hh = (const float*)d_in[9];
    const float* b_ih = (const float*)d_in[10];
    const float* b_hh = (const float*)d_in[11];
    float* out = (float*)d_out;

    float *p_cp, *p_ge;
    cudaGetSymbolAddress((void**)&p_cp, g_ctxproj);
    cudaGetSymbolAddress((void**)&p_ge, g_giemb);

    k_prep<<<1024, 256>>>(h0, Wq, W_hh, W_ih);
    k_emb<<<B * S, 128>>>(tgt, emb, out);

    // ctx_proj[B*L, H] = ctx @ Wc^T
    gemm_pre<<<dim3(H / 128, (B * L) / 64), 256>>>(ctx, CDIM, Wc, CDIM, p_cp, H, CDIM);
    // gi_emb[B*S, 3H] = emb_rows @ W_ih[:, :E]^T
    gemm_pre<<<dim3(G3 / 128, (B * S) / 64), 256>>>(out + H, OC, W_ih, XK, p_ge, G3, E);

    for (int t = 0; t < S; t++) {
        k1_q<<<64, 256>>>();
        k2_attn<<<B, 1024>>>(ctx, bq, v, out, t);
        k3_gates<<<288, 256>>>();
        k4_update<<<BH / 256, 256>>>(b_ih, b_hh, out, t);
    }
}